// round 3
// baseline (speedup 1.0000x reference)
#include <cuda_runtime.h>
#include <cuda_bf16.h>
#include <cstdint>
#include <math.h>

// ---------------- problem constants ----------------
#define N_IMG 2
#define R_TOT 159882
#define N_LVL 5
#define K_TOT 4507            // 1000+1000+1000+1000+507
#define POST_NMS 1000
#define NMS_THRESH 0.7f
#define IMG_MAX 800.0f
#define MIN_SIZE 1e-3f
#define BBOX_CLIP 4.135166556742356f   // log(1000/16) rounded to f32
#define MASK_WORDS 16                  // 16*64 = 1024 >= 1000 candidates

__constant__ int c_loff[N_LVL]  = {0, 120000, 150000, 157500, 159375};
__constant__ int c_lsize[N_LVL] = {120000, 30000, 7500, 1875, 507};
__constant__ int c_ksel[N_LVL]  = {1000, 1000, 1000, 1000, 507};
__constant__ int c_soff[N_LVL]  = {0, 1000, 2000, 3000, 4000};

// ---------------- scratch (device globals; no allocation allowed) ----------
__device__ int            g_cand_idx[N_IMG * K_TOT];
__device__ float4         g_cand_box[N_IMG * K_TOT];
__device__ float          g_cand_score[N_IMG * K_TOT];
__device__ unsigned char  g_cand_valid[N_IMG * K_TOT];
__device__ int            g_sorted_slot[N_IMG * K_TOT];
__device__ unsigned char  g_keep[N_IMG * K_TOT];

// ---------------- helpers ----------------
__device__ __forceinline__ unsigned mono_key(float f) {
    unsigned u = __float_as_uint(f);
    return (u & 0x80000000u) ? ~u : (u | 0x80000000u);
}

// block-wide ordered compaction scan (1024 threads): exclusive prefix of flag,
// *total gets block total.
__device__ __forceinline__ int block_scan_flag(bool flag, int* total) {
    __shared__ int wsum[32];
    int lane = threadIdx.x & 31;
    int wid  = threadIdx.x >> 5;
    unsigned ballot = __ballot_sync(0xffffffffu, flag);
    int lane_pref = __popc(ballot & ((1u << lane) - 1u));
    if (lane == 0) wsum[wid] = __popc(ballot);
    __syncthreads();
    if (wid == 0) {
        int v = wsum[lane];
        #pragma unroll
        for (int d = 1; d < 32; d <<= 1) {
            int x = __shfl_up_sync(0xffffffffu, v, d);
            if (lane >= d) v += x;
        }
        wsum[lane] = v;
    }
    __syncthreads();
    int excl = (wid == 0 ? 0 : wsum[wid - 1]) + lane_pref;
    *total = wsum[31];
    __syncthreads();
    return excl;
}

// ---------------- K1: per-(img,level) radix-select top-k ---------------------
// Produces g_cand_idx ordered EXACTLY like lax.top_k: objectness descending,
// ties by ascending original index. So slot == reference candidate position.
__global__ void topk_kernel(const float* __restrict__ obj) {
    const int img = blockIdx.x / N_LVL;
    const int lvl = blockIdx.x % N_LVL;
    const int n    = c_lsize[lvl];
    const int base = c_loff[lvl];
    const int k    = c_ksel[lvl];
    const float* src = obj + img * R_TOT + base;
    const int tid = threadIdx.x;

    __shared__ unsigned hist[2048];
    __shared__ unsigned sfx[2048];
    __shared__ unsigned sh_bstar, sh_kth;
    __shared__ unsigned long long skey[2048];
    __shared__ int c_sel;

    unsigned prefix = 0, pmask = 0, kth = (unsigned)k;
    const int shifts[3] = {21, 10, 0};
    const int nbits[3]  = {11, 11, 10};

    for (int pass = 0; pass < 3; ++pass) {
        const int shift = shifts[pass];
        const int bins  = 1 << nbits[pass];
        const unsigned bm = bins - 1;

        for (int b = tid; b < bins; b += 1024) hist[b] = 0;
        __syncthreads();
        for (int i = tid; i < n; i += 1024) {
            unsigned u = mono_key(src[i]);
            if ((u & pmask) == prefix) atomicAdd(&hist[(u >> shift) & bm], 1u);
        }
        __syncthreads();
        for (int b = tid; b < bins; b += 1024) sfx[b] = hist[b];
        __syncthreads();
        for (int d = 1; d < bins; d <<= 1) {           // suffix sums
            unsigned v0 = 0, v1 = 0;
            int b0 = tid, b1 = tid + 1024;
            if (b0 < bins) v0 = sfx[b0] + ((b0 + d < bins) ? sfx[b0 + d] : 0u);
            if (b1 < bins) v1 = sfx[b1] + ((b1 + d < bins) ? sfx[b1 + d] : 0u);
            __syncthreads();
            if (b0 < bins) sfx[b0] = v0;
            if (b1 < bins) sfx[b1] = v1;
            __syncthreads();
        }
        for (int b = tid; b < bins; b += 1024) {
            unsigned above = (b + 1 < bins) ? sfx[b + 1] : 0u;
            if (sfx[b] >= kth && above < kth) {
                sh_bstar = (unsigned)b;
                sh_kth   = kth - above;
            }
        }
        __syncthreads();
        prefix |= sh_bstar << shift;
        pmask  |= bm << shift;
        kth = sh_kth;
        __syncthreads();
    }

    const unsigned T = prefix;   // exact mono key of k-th largest

    // collect ALL elements with key >= T (count may slightly exceed k on ties)
    for (int t = tid; t < 2048; t += 1024) skey[t] = 0ull;
    if (tid == 0) c_sel = 0;
    __syncthreads();
    for (int i = tid; i < n; i += 1024) {
        unsigned u = mono_key(src[i]);
        if (u >= T) {
            int p = atomicAdd(&c_sel, 1);
            if (p < 2048)
                skey[p] = ((unsigned long long)u << 17) | (unsigned)(131071 - i);
        }
    }
    __syncthreads();

    // bitonic sort ascending over 2048 (1024 threads, 1 pair each)
    for (int k2 = 2; k2 <= 2048; k2 <<= 1) {
        for (int j = k2 >> 1; j > 0; j >>= 1) {
            int i2 = ((tid & ~(j - 1)) << 1) | (tid & (j - 1));
            int p2 = i2 + j;
            bool dir = ((i2 & k2) == 0);
            unsigned long long A = skey[i2], B = skey[p2];
            if ((A > B) == dir) { skey[i2] = B; skey[p2] = A; }
            __syncthreads();
        }
    }

    // t-th largest key = skey[2047 - t]: objectness desc, index asc on ties
    const int soff = img * K_TOT + c_soff[lvl];
    for (int t = tid; t < k; t += 1024) {
        unsigned long long key = skey[2047 - t];
        int i = 131071 - (int)(key & 0x1FFFFull);
        g_cand_idx[soff + t] = base + i;
    }
}

// ---------------- K2: gather + decode + clip + validity ----------------------
// Strictly unfused f32 arithmetic to mirror XLA elementwise ops.
__global__ void decode_kernel(const float* __restrict__ obj,
                              const float* __restrict__ deltas,
                              const float* __restrict__ anchors) {
    int t = blockIdx.x * blockDim.x + threadIdx.x;
    if (t >= N_IMG * K_TOT) return;
    const int img = t / K_TOT;
    g_keep[t] = 0;

    const int r = g_cand_idx[t];
    const float o = obj[img * R_TOT + r];
    const float score = __fdiv_rn(1.0f, __fadd_rn(1.0f, expf(-o)));

    const float* a = anchors + 4 * r;
    const float ax1 = a[0], ay1 = a[1], ax2 = a[2], ay2 = a[3];
    const float wa = __fsub_rn(ax2, ax1);
    const float ha = __fsub_rn(ay2, ay1);
    const float cxa = __fadd_rn(ax1, __fmul_rn(0.5f, wa));
    const float cya = __fadd_rn(ay1, __fmul_rn(0.5f, ha));

    const float* d = deltas + (size_t)(img * R_TOT + r) * 4;
    const float dx = d[0], dy = d[1];
    const float dw = fminf(d[2], BBOX_CLIP);
    const float dh = fminf(d[3], BBOX_CLIP);
    const float cx = __fadd_rn(__fmul_rn(dx, wa), cxa);
    const float cy = __fadd_rn(__fmul_rn(dy, ha), cya);
    const float w = __fmul_rn(expf(dw), wa);
    const float h = __fmul_rn(expf(dh), ha);

    float x1 = __fsub_rn(cx, __fmul_rn(0.5f, w));
    float y1 = __fsub_rn(cy, __fmul_rn(0.5f, h));
    float x2 = __fadd_rn(cx, __fmul_rn(0.5f, w));
    float y2 = __fadd_rn(cy, __fmul_rn(0.5f, h));
    x1 = fminf(fmaxf(x1, 0.0f), IMG_MAX);
    y1 = fminf(fmaxf(y1, 0.0f), IMG_MAX);
    x2 = fminf(fmaxf(x2, 0.0f), IMG_MAX);
    y2 = fminf(fmaxf(y2, 0.0f), IMG_MAX);

    bool valid = (__fsub_rn(x2, x1) >= MIN_SIZE) &&
                 (__fsub_rn(y2, y1) >= MIN_SIZE) &&
                 (score >= 0.0f);
    g_cand_box[t]   = make_float4(x1, y1, x2, y2);
    g_cand_score[t] = score;
    g_cand_valid[t] = valid ? 1 : 0;
}

// ---------------- K3: per-image global sort (stable tie-break by position) --
__global__ void sort_kernel() {
    extern __shared__ unsigned long long sk[];   // 8192 * 8B = 64KB
    const int img = blockIdx.x;
    const int tid = threadIdx.x;

    for (int i = tid; i < 8192; i += 1024) {
        unsigned long long key = 0ull;
        if (i < K_TOT) {
            float s = g_cand_valid[img * K_TOT + i] ? g_cand_score[img * K_TOT + i] : -1.0f;
            key = ((unsigned long long)mono_key(s) << 13) | (unsigned)(8191 - i);
        }
        sk[i] = key;
    }
    __syncthreads();

    for (int k2 = 2; k2 <= 8192; k2 <<= 1) {
        for (int j = k2 >> 1; j > 0; j >>= 1) {
            for (int t = tid; t < 4096; t += 1024) {
                int i = ((t & ~(j - 1)) << 1) | (t & (j - 1));
                int p = i + j;
                bool dir = ((i & k2) == 0);
                unsigned long long A = sk[i], B = sk[p];
                if ((A > B) == dir) { sk[i] = B; sk[p] = A; }
            }
            __syncthreads();
        }
    }
    for (int p = tid; p < K_TOT; p += 1024)
        g_sorted_slot[img * K_TOT + p] = 8191 - (int)(sk[8191 - p] & 0x1FFFull);
}

// ---------------- K4: per-(img,level) mask-based greedy NMS ------------------
// Phase A: collect level candidates in global-score order (as before).
// Phase B: build m x m suppression bit-matrix in parallel (IoU math identical
//          to the previously-passing kernel: offset boxes, __f*_rn ops).
// Phase C: single warp walks the greedy recurrence with a register-resident
//          removed-bitmask. No block barriers in the sequential part.
__global__ void nms_kernel() {
    extern __shared__ unsigned long long smask[];   // [1000][MASK_WORDS] = 128000 B
    const int img = blockIdx.x / N_LVL;
    const int lvl = blockIdx.x % N_LVL;
    const int s0 = c_soff[lvl];
    const int s1 = s0 + c_ksel[lvl];
    const int tid = threadIdx.x;
    const float off = (float)lvl * 801.0f;   // lvl * (max(H,W)+1)

    __shared__ float4 sbox[1000];            // OFFSET boxes
    __shared__ float  sarea[1000];
    __shared__ int    sgpos[1000];

    // ---- Phase A: collect ----
    int m = 0;
    for (int start = 0; start < K_TOT; start += 1024) {
        int p = start + tid;
        bool flag = false;
        int slot = -1;
        if (p < K_TOT) {
            slot = g_sorted_slot[img * K_TOT + p];
            flag = (slot >= s0) && (slot < s1) && (g_cand_valid[img * K_TOT + slot] != 0);
        }
        int total;
        int pos = block_scan_flag(flag, &total);
        if (flag) {
            int li = m + pos;
            float4 b = g_cand_box[img * K_TOT + slot];
            float ox1 = __fadd_rn(b.x, off);
            float oy1 = __fadd_rn(b.y, off);
            float ox2 = __fadd_rn(b.z, off);
            float oy2 = __fadd_rn(b.w, off);
            sbox[li]  = make_float4(ox1, oy1, ox2, oy2);
            sarea[li] = __fmul_rn(__fsub_rn(ox2, ox1), __fsub_rn(oy2, oy1));
            sgpos[li] = p;
        }
        m += total;
    }
    __syncthreads();

    // ---- Phase B: build suppression mask ----
    const int ntask = m * MASK_WORDS;
    for (int task = tid; task < ntask; task += 1024) {
        const int i = task >> 4;          // row (earlier candidate)
        const int w = task & (MASK_WORDS - 1);
        const float4 bi = sbox[i];
        const float ai = sarea[i];
        unsigned long long bits = 0ull;
        const int j0 = w << 6;
        const int jend = min(j0 + 64, m);
        for (int j = (j0 > i + 1 ? j0 : i + 1); j < jend; ++j) {
            float4 bj = sbox[j];
            float lx = fmaxf(bi.x, bj.x), ly = fmaxf(bi.y, bj.y);
            float rx = fminf(bi.z, bj.z), ry = fminf(bi.w, bj.w);
            float wx = fmaxf(__fsub_rn(rx, lx), 0.0f);
            float wy = fmaxf(__fsub_rn(ry, ly), 0.0f);
            float inter = __fmul_rn(wx, wy);
            float denom = __fadd_rn(__fsub_rn(__fadd_rn(ai, sarea[j]), inter), 1e-9f);
            float iou = __fdiv_rn(inter, denom);
            if (iou > NMS_THRESH) bits |= 1ull << (j - j0);
        }
        smask[task] = bits;
    }
    __syncthreads();

    // ---- Phase C: sequential greedy by warp 0 ----
    if (tid < 32) {
        const int lane = tid;
        unsigned long long remv = 0ull;   // lane l (< MASK_WORDS) holds removed word l
        for (int i = 0; i < m; ++i) {
            unsigned long long wv = __shfl_sync(0xffffffffu, remv, i >> 6);
            bool sup = (wv >> (i & 63)) & 1ull;
            if (!sup) {
                if (lane == 0) g_keep[img * K_TOT + sgpos[i]] = 1;
                if (lane < MASK_WORDS) remv |= smask[i * MASK_WORDS + lane];
            }
        }
    }
}

// ---------------- K5: compact kept (global score order) into outputs --------
__global__ void compact_kernel(float* __restrict__ out) {
    const int img = blockIdx.x;
    const int tid = threadIdx.x;
    float* out_b = out + img * (POST_NMS * 4);
    float* out_s = out + N_IMG * POST_NMS * 4 + img * POST_NMS;

    int rank_base = 0;
    for (int start = 0; start < K_TOT; start += 1024) {
        int p = start + tid;
        bool flag = (p < K_TOT) && (g_keep[img * K_TOT + p] != 0);
        int total;
        int pos = block_scan_flag(flag, &total);
        if (flag) {
            int rank = rank_base + pos;
            if (rank < POST_NMS) {
                int slot = g_sorted_slot[img * K_TOT + p];
                float4 b = g_cand_box[img * K_TOT + slot];
                out_b[rank * 4 + 0] = b.x;
                out_b[rank * 4 + 1] = b.y;
                out_b[rank * 4 + 2] = b.z;
                out_b[rank * 4 + 3] = b.w;
                out_s[rank] = g_cand_score[img * K_TOT + slot];
            }
        }
        rank_base += total;
    }
    int startr = rank_base < POST_NMS ? rank_base : POST_NMS;
    for (int r2 = startr + tid; r2 < POST_NMS; r2 += 1024) {
        out_b[r2 * 4 + 0] = 0.0f;
        out_b[r2 * 4 + 1] = 0.0f;
        out_b[r2 * 4 + 2] = 0.0f;
        out_b[r2 * 4 + 3] = 0.0f;
        out_s[r2] = -1.0f;
    }
}

// ---------------- launch -----------------------------------------------------
extern "C" void kernel_launch(void* const* d_in, const int* in_sizes, int n_in,
                              void* d_out, int out_size) {
    const float* objectness = (const float*)d_in[0];   // [2, 159882]
    const float* deltas     = (const float*)d_in[1];   // [2, 159882, 4]
    const float* anchors    = (const float*)d_in[2];   // [159882, 4]
    float* out = (float*)d_out;                        // boxes [2,1000,4] ++ scores [2,1000]

    cudaFuncSetAttribute(sort_kernel, cudaFuncAttributeMaxDynamicSharedMemorySize, 65536);
    cudaFuncSetAttribute(nms_kernel, cudaFuncAttributeMaxDynamicSharedMemorySize,
                         1000 * MASK_WORDS * 8);

    topk_kernel<<<N_IMG * N_LVL, 1024>>>(objectness);
    decode_kernel<<<(N_IMG * K_TOT + 255) / 256, 256>>>(objectness, deltas, anchors);
    sort_kernel<<<N_IMG, 1024, 65536>>>();
    nms_kernel<<<N_IMG * N_LVL, 1024, 1000 * MASK_WORDS * 8>>>();
    compact_kernel<<<N_IMG, 1024>>>(out);
}

// round 4
// speedup vs baseline: 1.0462x; 1.0462x over previous
#include <cuda_runtime.h>
#include <cuda_bf16.h>
#include <cstdint>
#include <math.h>

// ---------------- problem constants ----------------
#define N_IMG 2
#define R_TOT 159882
#define N_LVL 5
#define K_TOT 4507            // 1000+1000+1000+1000+507
#define POST_NMS 1000
#define NMS_THRESH 0.7f
#define IMG_MAX 800.0f
#define MIN_SIZE 1e-3f
#define BBOX_CLIP 4.135166556742356f   // log(1000/16) rounded to f32

__constant__ int c_loff[N_LVL]  = {0, 120000, 150000, 157500, 159375};
__constant__ int c_lsize[N_LVL] = {120000, 30000, 7500, 1875, 507};
__constant__ int c_ksel[N_LVL]  = {1000, 1000, 1000, 1000, 507};
__constant__ int c_soff[N_LVL]  = {0, 1000, 2000, 3000, 4000};

// ---------------- scratch (device globals; no allocation allowed) ----------
__device__ int            g_cand_idx[N_IMG * K_TOT];
__device__ float4         g_cand_box[N_IMG * K_TOT];    // raw clipped boxes
__device__ float          g_cand_score[N_IMG * K_TOT];
__device__ unsigned char  g_cand_valid[N_IMG * K_TOT];
// per-(img,level) kept lists (key-descending order), padded to 1024 slots
__device__ unsigned long long g_kept_key[N_IMG * N_LVL * 1024];
__device__ int                g_kept_slot[N_IMG * N_LVL * 1024];
__device__ int                g_kept_cnt[N_IMG * N_LVL];

// ---------------- helpers ----------------
__device__ __forceinline__ unsigned mono_key(float f) {
    unsigned u = __float_as_uint(f);
    return (u & 0x80000000u) ? ~u : (u | 0x80000000u);
}

// block-wide ordered compaction scan (1024 threads): exclusive prefix of flag,
// *total gets block total.
__device__ __forceinline__ int block_scan_flag(bool flag, int* total) {
    __shared__ int wsum[32];
    int lane = threadIdx.x & 31;
    int wid  = threadIdx.x >> 5;
    unsigned ballot = __ballot_sync(0xffffffffu, flag);
    int lane_pref = __popc(ballot & ((1u << lane) - 1u));
    if (lane == 0) wsum[wid] = __popc(ballot);
    __syncthreads();
    if (wid == 0) {
        int v = wsum[lane];
        #pragma unroll
        for (int d = 1; d < 32; d <<= 1) {
            int x = __shfl_up_sync(0xffffffffu, v, d);
            if (lane >= d) v += x;
        }
        wsum[lane] = v;
    }
    __syncthreads();
    int excl = (wid == 0 ? 0 : wsum[wid - 1]) + lane_pref;
    *total = wsum[31];
    __syncthreads();
    return excl;
}

// ---------------- K1: per-(img,level) radix-select top-k ---------------------
// Produces g_cand_idx ordered EXACTLY like lax.top_k: objectness descending,
// ties by ascending original index. So slot == reference candidate position.
__global__ void topk_kernel(const float* __restrict__ obj) {
    const int img = blockIdx.x / N_LVL;
    const int lvl = blockIdx.x % N_LVL;
    const int n    = c_lsize[lvl];
    const int base = c_loff[lvl];
    const int k    = c_ksel[lvl];
    const float* src = obj + img * R_TOT + base;
    const int tid = threadIdx.x;

    __shared__ unsigned hist[2048];
    __shared__ unsigned sfx[2048];
    __shared__ unsigned sh_bstar, sh_kth;
    __shared__ unsigned long long skey[2048];
    __shared__ int c_sel;

    unsigned prefix = 0, pmask = 0, kth = (unsigned)k;
    const int shifts[3] = {21, 10, 0};
    const int nbits[3]  = {11, 11, 10};

    for (int pass = 0; pass < 3; ++pass) {
        const int shift = shifts[pass];
        const int bins  = 1 << nbits[pass];
        const unsigned bm = bins - 1;

        for (int b = tid; b < bins; b += 1024) hist[b] = 0;
        __syncthreads();
        for (int i = tid; i < n; i += 1024) {
            unsigned u = mono_key(src[i]);
            if ((u & pmask) == prefix) atomicAdd(&hist[(u >> shift) & bm], 1u);
        }
        __syncthreads();
        for (int b = tid; b < bins; b += 1024) sfx[b] = hist[b];
        __syncthreads();
        for (int d = 1; d < bins; d <<= 1) {           // suffix sums
            unsigned v0 = 0, v1 = 0;
            int b0 = tid, b1 = tid + 1024;
            if (b0 < bins) v0 = sfx[b0] + ((b0 + d < bins) ? sfx[b0 + d] : 0u);
            if (b1 < bins) v1 = sfx[b1] + ((b1 + d < bins) ? sfx[b1 + d] : 0u);
            __syncthreads();
            if (b0 < bins) sfx[b0] = v0;
            if (b1 < bins) sfx[b1] = v1;
            __syncthreads();
        }
        for (int b = tid; b < bins; b += 1024) {
            unsigned above = (b + 1 < bins) ? sfx[b + 1] : 0u;
            if (sfx[b] >= kth && above < kth) {
                sh_bstar = (unsigned)b;
                sh_kth   = kth - above;
            }
        }
        __syncthreads();
        prefix |= sh_bstar << shift;
        pmask  |= bm << shift;
        kth = sh_kth;
        __syncthreads();
    }

    const unsigned T = prefix;   // exact mono key of k-th largest

    // collect ALL elements with key >= T (count may slightly exceed k on ties)
    for (int t = tid; t < 2048; t += 1024) skey[t] = 0ull;
    if (tid == 0) c_sel = 0;
    __syncthreads();
    for (int i = tid; i < n; i += 1024) {
        unsigned u = mono_key(src[i]);
        if (u >= T) {
            int p = atomicAdd(&c_sel, 1);
            if (p < 2048)
                skey[p] = ((unsigned long long)u << 17) | (unsigned)(131071 - i);
        }
    }
    __syncthreads();

    // bitonic sort ascending over 2048 (1024 threads, 1 pair each)
    for (int k2 = 2; k2 <= 2048; k2 <<= 1) {
        for (int j = k2 >> 1; j > 0; j >>= 1) {
            int i2 = ((tid & ~(j - 1)) << 1) | (tid & (j - 1));
            int p2 = i2 + j;
            bool dir = ((i2 & k2) == 0);
            unsigned long long A = skey[i2], B = skey[p2];
            if ((A > B) == dir) { skey[i2] = B; skey[p2] = A; }
            __syncthreads();
        }
    }

    // t-th largest key = skey[2047 - t]: objectness desc, index asc on ties
    const int soff = img * K_TOT + c_soff[lvl];
    for (int t = tid; t < k; t += 1024) {
        unsigned long long key = skey[2047 - t];
        int i = 131071 - (int)(key & 0x1FFFFull);
        g_cand_idx[soff + t] = base + i;
    }
}

// ---------------- K2: gather + decode + clip + validity ----------------------
// Strictly unfused f32 arithmetic to mirror XLA elementwise ops.
__global__ void decode_kernel(const float* __restrict__ obj,
                              const float* __restrict__ deltas,
                              const float* __restrict__ anchors) {
    int t = blockIdx.x * blockDim.x + threadIdx.x;
    if (t >= N_IMG * K_TOT) return;
    const int img = t / K_TOT;

    const int r = g_cand_idx[t];
    const float o = obj[img * R_TOT + r];
    const float score = __fdiv_rn(1.0f, __fadd_rn(1.0f, expf(-o)));

    const float* a = anchors + 4 * r;
    const float ax1 = a[0], ay1 = a[1], ax2 = a[2], ay2 = a[3];
    const float wa = __fsub_rn(ax2, ax1);
    const float ha = __fsub_rn(ay2, ay1);
    const float cxa = __fadd_rn(ax1, __fmul_rn(0.5f, wa));
    const float cya = __fadd_rn(ay1, __fmul_rn(0.5f, ha));

    const float* d = deltas + (size_t)(img * R_TOT + r) * 4;
    const float dx = d[0], dy = d[1];
    const float dw = fminf(d[2], BBOX_CLIP);
    const float dh = fminf(d[3], BBOX_CLIP);
    const float cx = __fadd_rn(__fmul_rn(dx, wa), cxa);
    const float cy = __fadd_rn(__fmul_rn(dy, ha), cya);
    const float w = __fmul_rn(expf(dw), wa);
    const float h = __fmul_rn(expf(dh), ha);

    float x1 = __fsub_rn(cx, __fmul_rn(0.5f, w));
    float y1 = __fsub_rn(cy, __fmul_rn(0.5f, h));
    float x2 = __fadd_rn(cx, __fmul_rn(0.5f, w));
    float y2 = __fadd_rn(cy, __fmul_rn(0.5f, h));
    x1 = fminf(fmaxf(x1, 0.0f), IMG_MAX);
    y1 = fminf(fmaxf(y1, 0.0f), IMG_MAX);
    x2 = fminf(fmaxf(x2, 0.0f), IMG_MAX);
    y2 = fminf(fmaxf(y2, 0.0f), IMG_MAX);

    bool valid = (__fsub_rn(x2, x1) >= MIN_SIZE) &&
                 (__fsub_rn(y2, y1) >= MIN_SIZE) &&
                 (score >= 0.0f);
    g_cand_box[t]   = make_float4(x1, y1, x2, y2);
    g_cand_score[t] = score;
    g_cand_valid[t] = valid ? 1 : 0;
}

// ---------------- K3: per-(img,level) chunked mask NMS -----------------------
// Cross-level IoU is exactly 0 (offset trick separation > image size), so the
// global greedy NMS decomposes into independent per-level greedy NMS over the
// level's candidates in (score desc, slot asc) order == slot order.
// Phase A: compact valid candidates (slot order) into shared memory.
// Phase B: full suppression bit-matrix (IoU math bit-identical to prior pass).
// Phase C: chunked greedy: 32x32 diagonal solved serially in registers by one
//          thread; cross-chunk suppression swept in parallel by 31 warps.
// Phase D: compact kept candidates to global per-level lists (key desc).
__global__ void nms_kernel() {
    extern __shared__ unsigned smask[];      // [1024][32] u32 bit-matrix (128KB)
    const int img = blockIdx.x / N_LVL;
    const int lvl = blockIdx.x % N_LVL;
    const int k  = c_ksel[lvl];
    const int s0 = c_soff[lvl];
    const int tid = threadIdx.x;
    const int lane = tid & 31;
    const int wid  = tid >> 5;
    const float off = (float)lvl * 801.0f;   // lvl * (max(H,W)+1)

    __shared__ float4 sbox[1024];            // OFFSET boxes
    __shared__ float  sarea[1024];
    __shared__ unsigned long long skeys[1024];
    __shared__ int    sslot[1024];
    __shared__ unsigned ssup[32];
    __shared__ unsigned skept[32];

    // ---- Phase A: compact valid (k <= 1024 -> single scan) ----
    bool flag = false;
    int slot = s0 + tid;                     // position within image's K_TOT
    if (tid < k) flag = (g_cand_valid[img * K_TOT + slot] != 0);
    int m;
    int pos = block_scan_flag(flag, &m);
    if (flag) {
        float4 b = g_cand_box[img * K_TOT + slot];
        float s  = g_cand_score[img * K_TOT + slot];
        float ox1 = __fadd_rn(b.x, off);
        float oy1 = __fadd_rn(b.y, off);
        float ox2 = __fadd_rn(b.z, off);
        float oy2 = __fadd_rn(b.w, off);
        sbox[pos]  = make_float4(ox1, oy1, ox2, oy2);
        sarea[pos] = __fmul_rn(__fsub_rn(ox2, ox1), __fsub_rn(oy2, oy1));
        skeys[pos] = ((unsigned long long)mono_key(s) << 13) | (unsigned)(8191 - slot);
        sslot[pos] = slot;
    }
    __syncthreads();

    // ---- Phase B: suppression bit matrix (upper triangle, j > i) ----
    const int ntask = m * 32;
    for (int task = tid; task < ntask; task += 1024) {
        const int i = task >> 5;
        const int w = task & 31;
        const int j0 = w << 5;
        const int jend = min(j0 + 32, m);
        const int jstart = max(j0, i + 1);
        unsigned bits = 0u;
        if (jstart < jend) {
            const float4 bi = sbox[i];
            const float ai = sarea[i];
            for (int j = jstart; j < jend; ++j) {
                float4 bj = sbox[j];
                float lx = fmaxf(bi.x, bj.x), ly = fmaxf(bi.y, bj.y);
                float rx = fminf(bi.z, bj.z), ry = fminf(bi.w, bj.w);
                float wx = fmaxf(__fsub_rn(rx, lx), 0.0f);
                float wy = fmaxf(__fsub_rn(ry, ly), 0.0f);
                float inter = __fmul_rn(wx, wy);
                float denom = __fadd_rn(__fsub_rn(__fadd_rn(ai, sarea[j]), inter), 1e-9f);
                float iou = __fdiv_rn(inter, denom);
                if (iou > NMS_THRESH) bits |= 1u << (j - j0);
            }
        }
        smask[task] = bits;                 // task == i*32 + w
    }
    if (tid < 32) { ssup[tid] = 0u; skept[tid] = 0u; }
    __syncthreads();

    // ---- Phase C: chunked greedy ----
    const int nchunks = (m + 31) >> 5;
    for (int c = 0; c < nchunks; ++c) {
        if (tid == 0) {
            unsigned sup = ssup[c];
            unsigned kept = 0u;
            const int jmax = min(32, m - (c << 5));
            const int rowbase = (c << 5) * 32 + c;
            for (int j = 0; j < jmax; ++j) {
                if (!((sup >> j) & 1u)) {
                    kept |= 1u << j;
                    sup |= smask[rowbase + j * 32];
                }
            }
            skept[c] = kept;
        }
        __syncthreads();
        const int wfut = c + 1 + wid;
        if (wfut < nchunks) {
            unsigned kept = skept[c];
            unsigned v = ((kept >> lane) & 1u) ? smask[((c << 5) + lane) * 32 + wfut] : 0u;
            unsigned red = __reduce_or_sync(0xffffffffu, v);
            if (lane == 0) ssup[wfut] |= red;
        }
        __syncthreads();
    }

    // ---- Phase D: compact kept to global (order preserved = key desc) ----
    bool kflag = (tid < m) && ((skept[tid >> 5] >> (tid & 31)) & 1u);
    int mkept;
    int kpos = block_scan_flag(kflag, &mkept);
    const int gbase = (img * N_LVL + lvl) * 1024;
    if (kflag) {
        g_kept_key[gbase + kpos]  = skeys[tid];
        g_kept_slot[gbase + kpos] = sslot[tid];
    }
    if (tid == 0) g_kept_cnt[img * N_LVL + lvl] = mkept;
}

// ---------------- K4: merge-rank kept lists + write outputs ------------------
// Each level's kept list is strictly descending in key. Global rank of a kept
// candidate = local index + sum over other levels of count-greater (binary
// search). Ranks form a permutation of 0..M-1.
__device__ __forceinline__ int count_greater(unsigned long long key,
                                             const unsigned long long* a, int n) {
    int lo = 0, hi = n;
    while (lo < hi) {
        int mid = (lo + hi) >> 1;
        if (a[mid] > key) lo = mid + 1; else hi = mid;
    }
    return lo;
}

__global__ void out_kernel(float* __restrict__ out) {
    const int img = blockIdx.x;
    const int tid = threadIdx.x;
    float* out_b = out + img * (POST_NMS * 4);
    float* out_s = out + N_IMG * POST_NMS * 4 + img * POST_NMS;

    __shared__ int cnt[N_LVL], offp[N_LVL + 1];
    if (tid == 0) {
        int acc = 0;
        for (int l = 0; l < N_LVL; ++l) {
            cnt[l] = g_kept_cnt[img * N_LVL + l];
            offp[l] = acc;
            acc += cnt[l];
        }
        offp[N_LVL] = acc;
    }
    __syncthreads();
    const int M = offp[N_LVL];

    // default-fill slots that no kept candidate will claim
    for (int r = tid; r < POST_NMS; r += 1024) {
        if (r >= M) {
            out_b[r * 4 + 0] = 0.0f;
            out_b[r * 4 + 1] = 0.0f;
            out_b[r * 4 + 2] = 0.0f;
            out_b[r * 4 + 3] = 0.0f;
            out_s[r] = -1.0f;
        }
    }

    for (int idx = tid; idx < M; idx += 1024) {
        int L = 0;
        while (idx >= offp[L + 1]) ++L;
        const int i = idx - offp[L];
        const unsigned long long key = g_kept_key[(img * N_LVL + L) * 1024 + i];
        int rank = i;
        #pragma unroll
        for (int L2 = 0; L2 < N_LVL; ++L2) {
            if (L2 == L) continue;
            rank += count_greater(key, &g_kept_key[(img * N_LVL + L2) * 1024], cnt[L2]);
        }
        if (rank < POST_NMS) {
            const int slot = g_kept_slot[(img * N_LVL + L) * 1024 + i];
            float4 b = g_cand_box[img * K_TOT + slot];
            out_b[rank * 4 + 0] = b.x;
            out_b[rank * 4 + 1] = b.y;
            out_b[rank * 4 + 2] = b.z;
            out_b[rank * 4 + 3] = b.w;
            out_s[rank] = g_cand_score[img * K_TOT + slot];
        }
    }
}

// ---------------- launch -----------------------------------------------------
extern "C" void kernel_launch(void* const* d_in, const int* in_sizes, int n_in,
                              void* d_out, int out_size) {
    const float* objectness = (const float*)d_in[0];   // [2, 159882]
    const float* deltas     = (const float*)d_in[1];   // [2, 159882, 4]
    const float* anchors    = (const float*)d_in[2];   // [159882, 4]
    float* out = (float*)d_out;                        // boxes [2,1000,4] ++ scores [2,1000]

    const int mask_bytes = 1024 * 32 * (int)sizeof(unsigned);   // 128KB
    cudaFuncSetAttribute(nms_kernel, cudaFuncAttributeMaxDynamicSharedMemorySize, mask_bytes);

    topk_kernel<<<N_IMG * N_LVL, 1024>>>(objectness);
    decode_kernel<<<(N_IMG * K_TOT + 255) / 256, 256>>>(objectness, deltas, anchors);
    nms_kernel<<<N_IMG * N_LVL, 1024, mask_bytes>>>();
    out_kernel<<<N_IMG, 1024>>>(out);
}

// round 5
// speedup vs baseline: 2.8310x; 2.7060x over previous
#include <cuda_runtime.h>
#include <cuda_bf16.h>
#include <cstdint>
#include <math.h>

// ---------------- problem constants ----------------
#define N_IMG 2
#define R_TOT 159882
#define N_LVL 5
#define K_TOT 4507            // 1000+1000+1000+1000+507
#define POST_NMS 1000
#define NMS_THRESH 0.7f
#define IMG_MAX 800.0f
#define MIN_SIZE 1e-3f
#define BBOX_CLIP 4.135166556742356f   // log(1000/16) rounded to f32

__constant__ int c_loff[N_LVL]  = {0, 120000, 150000, 157500, 159375};
__constant__ int c_lsize[N_LVL] = {120000, 30000, 7500, 1875, 507};
__constant__ int c_ksel[N_LVL]  = {1000, 1000, 1000, 1000, 507};
__constant__ int c_soff[N_LVL]  = {0, 1000, 2000, 3000, 4000};

// ---------------- scratch (device globals; no allocation allowed) ----------
__device__ int            g_cand_idx[N_IMG * K_TOT];
__device__ float4         g_cand_box[N_IMG * K_TOT];    // raw clipped boxes
__device__ float          g_cand_score[N_IMG * K_TOT];
__device__ unsigned char  g_cand_valid[N_IMG * K_TOT];
// per-(img,level) kept lists (key-descending order), padded to 1024 slots
__device__ unsigned long long g_kept_key[N_IMG * N_LVL * 1024];
__device__ int                g_kept_slot[N_IMG * N_LVL * 1024];
__device__ int                g_kept_cnt[N_IMG * N_LVL];

// ---------------- helpers ----------------
__device__ __forceinline__ unsigned mono_key(float f) {
    unsigned u = __float_as_uint(f);
    return (u & 0x80000000u) ? ~u : (u | 0x80000000u);
}

// block-wide ordered compaction scan (1024 threads): exclusive prefix of flag,
// *total gets block total.
__device__ __forceinline__ int block_scan_flag(bool flag, int* total) {
    __shared__ int wsum[32];
    int lane = threadIdx.x & 31;
    int wid  = threadIdx.x >> 5;
    unsigned ballot = __ballot_sync(0xffffffffu, flag);
    int lane_pref = __popc(ballot & ((1u << lane) - 1u));
    if (lane == 0) wsum[wid] = __popc(ballot);
    __syncthreads();
    if (wid == 0) {
        int v = wsum[lane];
        #pragma unroll
        for (int d = 1; d < 32; d <<= 1) {
            int x = __shfl_up_sync(0xffffffffu, v, d);
            if (lane >= d) v += x;
        }
        wsum[lane] = v;
    }
    __syncthreads();
    int excl = (wid == 0 ? 0 : wsum[wid - 1]) + lane_pref;
    *total = wsum[31];
    __syncthreads();
    return excl;
}

// ---------------- K1: per-(img,level) radix-select top-k ---------------------
__global__ void topk_kernel(const float* __restrict__ obj) {
    const int img = blockIdx.x / N_LVL;
    const int lvl = blockIdx.x % N_LVL;
    const int n    = c_lsize[lvl];
    const int base = c_loff[lvl];
    const int k    = c_ksel[lvl];
    const float* src = obj + img * R_TOT + base;
    const int tid = threadIdx.x;

    __shared__ unsigned hist[2048];
    __shared__ unsigned sfx[2048];
    __shared__ unsigned sh_bstar, sh_kth;
    __shared__ unsigned long long skey[2048];
    __shared__ int c_sel;

    unsigned prefix = 0, pmask = 0, kth = (unsigned)k;
    const int shifts[3] = {21, 10, 0};
    const int nbits[3]  = {11, 11, 10};

    for (int pass = 0; pass < 3; ++pass) {
        const int shift = shifts[pass];
        const int bins  = 1 << nbits[pass];
        const unsigned bm = bins - 1;

        for (int b = tid; b < bins; b += 1024) hist[b] = 0;
        __syncthreads();
        for (int i = tid; i < n; i += 1024) {
            unsigned u = mono_key(src[i]);
            if ((u & pmask) == prefix) atomicAdd(&hist[(u >> shift) & bm], 1u);
        }
        __syncthreads();
        for (int b = tid; b < bins; b += 1024) sfx[b] = hist[b];
        __syncthreads();
        for (int d = 1; d < bins; d <<= 1) {           // suffix sums
            unsigned v0 = 0, v1 = 0;
            int b0 = tid, b1 = tid + 1024;
            if (b0 < bins) v0 = sfx[b0] + ((b0 + d < bins) ? sfx[b0 + d] : 0u);
            if (b1 < bins) v1 = sfx[b1] + ((b1 + d < bins) ? sfx[b1 + d] : 0u);
            __syncthreads();
            if (b0 < bins) sfx[b0] = v0;
            if (b1 < bins) sfx[b1] = v1;
            __syncthreads();
        }
        for (int b = tid; b < bins; b += 1024) {
            unsigned above = (b + 1 < bins) ? sfx[b + 1] : 0u;
            if (sfx[b] >= kth && above < kth) {
                sh_bstar = (unsigned)b;
                sh_kth   = kth - above;
            }
        }
        __syncthreads();
        prefix |= sh_bstar << shift;
        pmask  |= bm << shift;
        kth = sh_kth;
        __syncthreads();
    }

    const unsigned T = prefix;   // exact mono key of k-th largest

    for (int t = tid; t < 2048; t += 1024) skey[t] = 0ull;
    if (tid == 0) c_sel = 0;
    __syncthreads();
    for (int i = tid; i < n; i += 1024) {
        unsigned u = mono_key(src[i]);
        if (u >= T) {
            int p = atomicAdd(&c_sel, 1);
            if (p < 2048)
                skey[p] = ((unsigned long long)u << 17) | (unsigned)(131071 - i);
        }
    }
    __syncthreads();

    for (int k2 = 2; k2 <= 2048; k2 <<= 1) {
        for (int j = k2 >> 1; j > 0; j >>= 1) {
            int i2 = ((tid & ~(j - 1)) << 1) | (tid & (j - 1));
            int p2 = i2 + j;
            bool dir = ((i2 & k2) == 0);
            unsigned long long A = skey[i2], B = skey[p2];
            if ((A > B) == dir) { skey[i2] = B; skey[p2] = A; }
            __syncthreads();
        }
    }

    const int soff = img * K_TOT + c_soff[lvl];
    for (int t = tid; t < k; t += 1024) {
        unsigned long long key = skey[2047 - t];
        int i = 131071 - (int)(key & 0x1FFFFull);
        g_cand_idx[soff + t] = base + i;
    }
}

// ---------------- K2: gather + decode + clip + validity ----------------------
__global__ void decode_kernel(const float* __restrict__ obj,
                              const float* __restrict__ deltas,
                              const float* __restrict__ anchors) {
    int t = blockIdx.x * blockDim.x + threadIdx.x;
    if (t >= N_IMG * K_TOT) return;
    const int img = t / K_TOT;

    const int r = g_cand_idx[t];
    const float o = obj[img * R_TOT + r];
    const float score = __fdiv_rn(1.0f, __fadd_rn(1.0f, expf(-o)));

    const float* a = anchors + 4 * r;
    const float ax1 = a[0], ay1 = a[1], ax2 = a[2], ay2 = a[3];
    const float wa = __fsub_rn(ax2, ax1);
    const float ha = __fsub_rn(ay2, ay1);
    const float cxa = __fadd_rn(ax1, __fmul_rn(0.5f, wa));
    const float cya = __fadd_rn(ay1, __fmul_rn(0.5f, ha));

    const float* d = deltas + (size_t)(img * R_TOT + r) * 4;
    const float dx = d[0], dy = d[1];
    const float dw = fminf(d[2], BBOX_CLIP);
    const float dh = fminf(d[3], BBOX_CLIP);
    const float cx = __fadd_rn(__fmul_rn(dx, wa), cxa);
    const float cy = __fadd_rn(__fmul_rn(dy, ha), cya);
    const float w = __fmul_rn(expf(dw), wa);
    const float h = __fmul_rn(expf(dh), ha);

    float x1 = __fsub_rn(cx, __fmul_rn(0.5f, w));
    float y1 = __fsub_rn(cy, __fmul_rn(0.5f, h));
    float x2 = __fadd_rn(cx, __fmul_rn(0.5f, w));
    float y2 = __fadd_rn(cy, __fmul_rn(0.5f, h));
    x1 = fminf(fmaxf(x1, 0.0f), IMG_MAX);
    y1 = fminf(fmaxf(y1, 0.0f), IMG_MAX);
    x2 = fminf(fmaxf(x2, 0.0f), IMG_MAX);
    y2 = fminf(fmaxf(y2, 0.0f), IMG_MAX);

    bool valid = (__fsub_rn(x2, x1) >= MIN_SIZE) &&
                 (__fsub_rn(y2, y1) >= MIN_SIZE) &&
                 (score >= 0.0f);
    g_cand_box[t]   = make_float4(x1, y1, x2, y2);
    g_cand_score[t] = score;
    g_cand_valid[t] = valid ? 1 : 0;
}

// ---------------- K3: per-(img,level) chunked mask NMS -----------------------
// smask layout TRANSPOSED: smask[w * 1024 + i] = suppression bits of row i,
// word w (bit b = candidate w*32+b suppressed-by-i). Conflict-free everywhere.
__global__ void nms_kernel() {
    extern __shared__ unsigned smask[];      // [32][1024] u32 (128KB)
    const int img = blockIdx.x / N_LVL;
    const int lvl = blockIdx.x % N_LVL;
    const int k  = c_ksel[lvl];
    const int s0 = c_soff[lvl];
    const int tid = threadIdx.x;
    const int lane = tid & 31;
    const int wid  = tid >> 5;
    const float off = (float)lvl * 801.0f;   // lvl * (max(H,W)+1)

    __shared__ float4 sbox[1024];            // OFFSET boxes
    __shared__ float  sarea[1024];
    __shared__ unsigned long long skeys[1024];
    __shared__ int    sslot[1024];
    __shared__ unsigned ssup[32];
    __shared__ unsigned skept[32];

    // ---- Phase A: compact valid (k <= 1024 -> single scan) ----
    bool flag = false;
    int slot = s0 + tid;
    if (tid < k) flag = (g_cand_valid[img * K_TOT + slot] != 0);
    int m;
    int pos = block_scan_flag(flag, &m);
    if (flag) {
        float4 b = g_cand_box[img * K_TOT + slot];
        float s  = g_cand_score[img * K_TOT + slot];
        float ox1 = __fadd_rn(b.x, off);
        float oy1 = __fadd_rn(b.y, off);
        float ox2 = __fadd_rn(b.z, off);
        float oy2 = __fadd_rn(b.w, off);
        sbox[pos]  = make_float4(ox1, oy1, ox2, oy2);
        sarea[pos] = __fmul_rn(__fsub_rn(ox2, ox1), __fsub_rn(oy2, oy1));
        skeys[pos] = ((unsigned long long)mono_key(s) << 13) | (unsigned)(8191 - slot);
        sslot[pos] = slot;
    }
    if (tid < 32) { ssup[tid] = 0u; skept[tid] = 0u; }
    __syncthreads();

    const int nchunks = (m + 31) >> 5;

    // ---- Phase B: warp-per-row bit matrix; lane = j within word ----
    // Row i needs words w in [i>>5, nchunks). Lanes read consecutive sbox[j]
    // (conflict-free); ballot assembles the word. inter>0 early-out skips
    // the divide without changing any decision (inter==0 => iou==0).
    for (int i = wid; i < m; i += 32) {
        const float4 bi = sbox[i];
        const float ai = sarea[i];
        for (int w = i >> 5; w < nchunks; ++w) {
            const int j = (w << 5) + lane;
            bool sup = false;
            if (j > i && j < m) {
                float4 bj = sbox[j];
                float lx = fmaxf(bi.x, bj.x), ly = fmaxf(bi.y, bj.y);
                float rx = fminf(bi.z, bj.z), ry = fminf(bi.w, bj.w);
                float wx = fmaxf(__fsub_rn(rx, lx), 0.0f);
                float wy = fmaxf(__fsub_rn(ry, ly), 0.0f);
                float inter = __fmul_rn(wx, wy);
                if (inter > 0.0f) {
                    float denom = __fadd_rn(__fsub_rn(__fadd_rn(ai, sarea[j]), inter), 1e-9f);
                    float iou = __fdiv_rn(inter, denom);
                    sup = iou > NMS_THRESH;
                }
            }
            unsigned bits = __ballot_sync(0xffffffffu, sup);
            if (lane == 0) smask[w * 1024 + i] = bits;
        }
    }
    __syncthreads();

    // ---- Phase C: chunked greedy (32 serial chunk-steps) ----
    for (int c = 0; c < nchunks; ++c) {
        if (tid == 0) {
            unsigned sup = ssup[c];
            unsigned kept = 0u;
            const int jmax = min(32, m - (c << 5));
            const unsigned* diag = &smask[c * 1024 + (c << 5)];
            for (int j = 0; j < jmax; ++j) {
                if (!((sup >> j) & 1u)) {
                    kept |= 1u << j;
                    sup |= diag[j];
                }
            }
            skept[c] = kept;
        }
        __syncthreads();
        const int wfut = c + 1 + wid;
        if (wfut < nchunks) {
            unsigned kept = skept[c];
            unsigned v = ((kept >> lane) & 1u) ? smask[wfut * 1024 + (c << 5) + lane] : 0u;
            unsigned red = __reduce_or_sync(0xffffffffu, v);
            if (lane == 0) ssup[wfut] |= red;
        }
        __syncthreads();
    }

    // ---- Phase D: compact kept to global (order preserved = key desc) ----
    bool kflag = (tid < m) && ((skept[tid >> 5] >> (tid & 31)) & 1u);
    int mkept;
    int kpos = block_scan_flag(kflag, &mkept);
    const int gbase = (img * N_LVL + lvl) * 1024;
    if (kflag) {
        g_kept_key[gbase + kpos]  = skeys[tid];
        g_kept_slot[gbase + kpos] = sslot[tid];
    }
    if (tid == 0) g_kept_cnt[img * N_LVL + lvl] = mkept;
}

// ---------------- K4: merge-rank kept lists + write outputs ------------------
__global__ void out_kernel(float* __restrict__ out) {
    const int img = blockIdx.x;
    const int tid = threadIdx.x;
    float* out_b = out + img * (POST_NMS * 4);
    float* out_s = out + N_IMG * POST_NMS * 4 + img * POST_NMS;

    __shared__ unsigned long long skeys[N_LVL * 1024];   // 40KB
    __shared__ int cnt[N_LVL], offp[N_LVL + 1];
    if (tid == 0) {
        int acc = 0;
        for (int l = 0; l < N_LVL; ++l) {
            cnt[l] = g_kept_cnt[img * N_LVL + l];
            offp[l] = acc;
            acc += cnt[l];
        }
        offp[N_LVL] = acc;
    }
    __syncthreads();
    // stage kept keys into shared
    for (int l = 0; l < N_LVL; ++l)
        for (int i = tid; i < cnt[l]; i += 1024)
            skeys[l * 1024 + i] = g_kept_key[(img * N_LVL + l) * 1024 + i];
    __syncthreads();
    const int M = offp[N_LVL];

    for (int r = tid; r < POST_NMS; r += 1024) {
        if (r >= M) {
            out_b[r * 4 + 0] = 0.0f;
            out_b[r * 4 + 1] = 0.0f;
            out_b[r * 4 + 2] = 0.0f;
            out_b[r * 4 + 3] = 0.0f;
            out_s[r] = -1.0f;
        }
    }

    for (int idx = tid; idx < M; idx += 1024) {
        int L = 0;
        while (idx >= offp[L + 1]) ++L;
        const int i = idx - offp[L];
        const unsigned long long key = skeys[L * 1024 + i];
        int rank = i;
        #pragma unroll
        for (int L2 = 0; L2 < N_LVL; ++L2) {
            if (L2 == L) continue;
            const unsigned long long* a = &skeys[L2 * 1024];
            int lo = 0, hi = cnt[L2];
            while (lo < hi) {
                int mid = (lo + hi) >> 1;
                if (a[mid] > key) lo = mid + 1; else hi = mid;
            }
            rank += lo;
        }
        if (rank < POST_NMS) {
            const int slot = g_kept_slot[(img * N_LVL + L) * 1024 + i];
            float4 b = g_cand_box[img * K_TOT + slot];
            out_b[rank * 4 + 0] = b.x;
            out_b[rank * 4 + 1] = b.y;
            out_b[rank * 4 + 2] = b.z;
            out_b[rank * 4 + 3] = b.w;
            out_s[rank] = g_cand_score[img * K_TOT + slot];
        }
    }
}

// ---------------- launch -----------------------------------------------------
extern "C" void kernel_launch(void* const* d_in, const int* in_sizes, int n_in,
                              void* d_out, int out_size) {
    const float* objectness = (const float*)d_in[0];   // [2, 159882]
    const float* deltas     = (const float*)d_in[1];   // [2, 159882, 4]
    const float* anchors    = (const float*)d_in[2];   // [159882, 4]
    float* out = (float*)d_out;                        // boxes [2,1000,4] ++ scores [2,1000]

    const int mask_bytes = 32 * 1024 * (int)sizeof(unsigned);   // 128KB
    cudaFuncSetAttribute(nms_kernel, cudaFuncAttributeMaxDynamicSharedMemorySize, mask_bytes);

    topk_kernel<<<N_IMG * N_LVL, 1024>>>(objectness);
    decode_kernel<<<(N_IMG * K_TOT + 255) / 256, 256>>>(objectness, deltas, anchors);
    nms_kernel<<<N_IMG * N_LVL, 1024, mask_bytes>>>();
    out_kernel<<<N_IMG, 1024>>>(out);
}

// round 6
// speedup vs baseline: 6.2193x; 2.1968x over previous
#include <cuda_runtime.h>
#include <cuda_bf16.h>
#include <cstdint>
#include <math.h>

// ---------------- problem constants ----------------
#define N_IMG 2
#define R_TOT 159882
#define N_LVL 5
#define POST_NMS 1000
#define NMS_THRESH 0.7f
#define IMG_MAX 800.0f
#define MIN_SIZE 1e-3f
#define BBOX_CLIP 4.135166556742356f   // log(1000/16) rounded to f32

__constant__ int c_loff[N_LVL]  = {0, 120000, 150000, 157500, 159375};
__constant__ int c_lsize[N_LVL] = {120000, 30000, 7500, 1875, 507};
__constant__ int c_ksel[N_LVL]  = {1000, 1000, 1000, 1000, 507};
__constant__ int c_soff[N_LVL]  = {0, 1000, 2000, 3000, 4000};

// ---------------- scratch (device globals; no allocation allowed) ----------
// per (img,level) ("il" = img*5+lvl), compacted NMS candidate lists:
__device__ int                g_ncnt[N_IMG * N_LVL];
__device__ float4             g_nbox [N_IMG * N_LVL * 1024];  // OFFSET boxes
__device__ float              g_narea[N_IMG * N_LVL * 1024];
__device__ unsigned long long g_nkey [N_IMG * N_LVL * 1024];
__device__ int                g_npos [N_IMG * N_LVL * 1024];  // within-level p
// raw (unoffset) boxes + scores indexed by within-level p:
__device__ float4             g_rawbox[N_IMG * N_LVL * 1024];
__device__ float              g_rawsc [N_IMG * N_LVL * 1024];
// suppression bit-matrix, layout [il][w*1024 + i]:
__device__ unsigned           g_mask[N_IMG * N_LVL * 32 * 1024];
// kept lists (key-descending):
__device__ unsigned long long g_kept_key[N_IMG * N_LVL * 1024];
__device__ int                g_kept_p  [N_IMG * N_LVL * 1024];
__device__ int                g_kept_cnt[N_IMG * N_LVL];

// ---------------- helpers ----------------
__device__ __forceinline__ unsigned mono_key(float f) {
    unsigned u = __float_as_uint(f);
    return (u & 0x80000000u) ? ~u : (u | 0x80000000u);
}
__device__ __forceinline__ float mono_inv(unsigned m) {
    unsigned u = (m & 0x80000000u) ? (m & 0x7fffffffu) : ~m;
    return __uint_as_float(u);
}

// block-wide ordered compaction scan (1024 threads)
__device__ __forceinline__ int block_scan_flag(bool flag, int* total) {
    __shared__ int wsum[32];
    int lane = threadIdx.x & 31;
    int wid  = threadIdx.x >> 5;
    unsigned ballot = __ballot_sync(0xffffffffu, flag);
    int lane_pref = __popc(ballot & ((1u << lane) - 1u));
    if (lane == 0) wsum[wid] = __popc(ballot);
    __syncthreads();
    if (wid == 0) {
        int v = wsum[lane];
        #pragma unroll
        for (int d = 1; d < 32; d <<= 1) {
            int x = __shfl_up_sync(0xffffffffu, v, d);
            if (lane >= d) v += x;
        }
        wsum[lane] = v;
    }
    __syncthreads();
    int excl = (wid == 0 ? 0 : wsum[wid - 1]) + lane_pref;
    *total = wsum[31];
    __syncthreads();
    return excl;
}

// ============ K1: radix-select top-k + sort + decode + compact ===============
__global__ void topk_decode_kernel(const float* __restrict__ obj,
                                   const float* __restrict__ deltas,
                                   const float* __restrict__ anchors,
                                   float* __restrict__ out) {
    const int il  = blockIdx.x;
    const int img = il / N_LVL;
    const int lvl = il % N_LVL;
    const int n    = c_lsize[lvl];
    const int base = c_loff[lvl];
    const int k    = c_ksel[lvl];
    const float* src = obj + img * R_TOT + base;
    const int tid  = threadIdx.x;
    const int lane = tid & 31;
    const int wrp  = tid >> 5;

    __shared__ unsigned hist[2048];
    __shared__ unsigned wtot[32], wtot2[32];
    __shared__ unsigned sh_bstar, sh_kth;
    __shared__ unsigned long long skey[2048];
    __shared__ int c_sel;

    // default-fill outputs (once per image; lvl==0 block)
    if (lvl == 0) {
        float* ob = out + img * (POST_NMS * 4);
        float* os = out + N_IMG * POST_NMS * 4 + img * POST_NMS;
        for (int x = tid; x < POST_NMS * 4; x += 1024) ob[x] = 0.0f;
        for (int x = tid; x < POST_NMS; x += 1024) os[x] = -1.0f;
    }

    unsigned prefix = 0, pmask = 0, kth = (unsigned)k;
    const int shifts[3] = {21, 10, 0};
    const int nbits[3]  = {11, 11, 10};

    for (int pass = 0; pass < 3; ++pass) {
        const int shift = shifts[pass];
        const int bins  = 1 << nbits[pass];
        const unsigned bm = bins - 1;

        for (int b = tid; b < bins; b += 1024) hist[b] = 0;
        __syncthreads();
        for (int i = tid; i < n; i += 1024) {
            unsigned u = mono_key(src[i]);
            if ((u & pmask) == prefix) atomicAdd(&hist[(u >> shift) & bm], 1u);
        }
        __syncthreads();

        // hierarchical suffix-sum over pairs (thread owns bins 2t, 2t+1)
        const int bin0 = 2 * tid, bin1 = 2 * tid + 1;
        unsigned e0 = (bin0 < bins) ? hist[bin0] : 0u;
        unsigned e1 = (bin1 < bins) ? hist[bin1] : 0u;
        unsigned s = e0 + e1;
        unsigned S = s;
        #pragma unroll
        for (int d = 1; d < 32; d <<= 1) {
            unsigned x = __shfl_down_sync(0xffffffffu, S, d);
            if (lane + d < 32) S += x;
        }
        if (lane == 0) wtot[wrp] = S;
        __syncthreads();
        if (wrp == 0) {
            unsigned t2 = wtot[lane];
            unsigned W = t2;
            #pragma unroll
            for (int d = 1; d < 32; d <<= 1) {
                unsigned x = __shfl_down_sync(0xffffffffu, W, d);
                if (lane + d < 32) W += x;
            }
            wtot2[lane] = W;
        }
        __syncthreads();
        unsigned after_warp = (wrp < 31) ? wtot2[wrp + 1] : 0u;
        unsigned sfx_after = (S - s) + after_warp;    // suffix strictly after pair
        // boundary find: suffix(b) >= kth && suffix(b+1) < kth
        unsigned sfx1 = e1 + sfx_after;               // suffix at bin1
        unsigned sfx0 = s + sfx_after;                // suffix at bin0
        if (bin0 < bins && sfx0 >= kth && sfx1 < kth) { sh_bstar = (unsigned)bin0; sh_kth = kth - sfx1; }
        if (bin1 < bins && sfx1 >= kth && sfx_after < kth) { sh_bstar = (unsigned)bin1; sh_kth = kth - sfx_after; }
        __syncthreads();
        prefix |= sh_bstar << shift;
        pmask  |= bm << shift;
        kth = sh_kth;
        __syncthreads();
    }

    const unsigned T = prefix;   // exact mono key of k-th largest

    // collect all >= T
    for (int t = tid; t < 2048; t += 1024) skey[t] = 0ull;
    if (tid == 0) c_sel = 0;
    __syncthreads();
    for (int i = tid; i < n; i += 1024) {
        unsigned u = mono_key(src[i]);
        if (u >= T) {
            int p = atomicAdd(&c_sel, 1);
            if (p < 2048)
                skey[p] = ((unsigned long long)u << 17) | (unsigned)(131071 - i);
        }
    }
    __syncthreads();

    // size-adaptive bitonic sort ascending
    int csel = min(c_sel, 2048);
    int sortN = 512;
    while (sortN < csel) sortN <<= 1;
    const int npairs = sortN >> 1;
    for (int k2 = 2; k2 <= sortN; k2 <<= 1) {
        for (int j = k2 >> 1; j > 0; j >>= 1) {
            if (tid < npairs) {
                int i2 = ((tid & ~(j - 1)) << 1) | (tid & (j - 1));
                int p2 = i2 + j;
                bool dir = ((i2 & k2) == 0);
                unsigned long long A = skey[i2], B = skey[p2];
                if ((A > B) == dir) { skey[i2] = B; skey[p2] = A; }
            }
            __syncthreads();
        }
    }

    // decode candidate p = tid (objectness recovered from the sort key)
    bool flag = false;
    float4 rbox = make_float4(0.f, 0.f, 0.f, 0.f);
    float4 obox = rbox;
    float area = 0.f, score = 0.f;
    if (tid < k) {
        unsigned long long kk = skey[sortN - 1 - tid];
        int i = 131071 - (int)(kk & 0x1FFFFull);
        int r = base + i;
        const float o = mono_inv((unsigned)(kk >> 17));
        score = __fdiv_rn(1.0f, __fadd_rn(1.0f, expf(-o)));

        float4 a = *(const float4*)(anchors + 4 * r);
        const float wa = __fsub_rn(a.z, a.x);
        const float ha = __fsub_rn(a.w, a.y);
        const float cxa = __fadd_rn(a.x, __fmul_rn(0.5f, wa));
        const float cya = __fadd_rn(a.y, __fmul_rn(0.5f, ha));

        float4 d = *(const float4*)(deltas + (size_t)(img * R_TOT + r) * 4);
        const float dw = fminf(d.z, BBOX_CLIP);
        const float dh = fminf(d.w, BBOX_CLIP);
        const float cx = __fadd_rn(__fmul_rn(d.x, wa), cxa);
        const float cy = __fadd_rn(__fmul_rn(d.y, ha), cya);
        const float w = __fmul_rn(expf(dw), wa);
        const float h = __fmul_rn(expf(dh), ha);

        float x1 = __fsub_rn(cx, __fmul_rn(0.5f, w));
        float y1 = __fsub_rn(cy, __fmul_rn(0.5f, h));
        float x2 = __fadd_rn(cx, __fmul_rn(0.5f, w));
        float y2 = __fadd_rn(cy, __fmul_rn(0.5f, h));
        x1 = fminf(fmaxf(x1, 0.0f), IMG_MAX);
        y1 = fminf(fmaxf(y1, 0.0f), IMG_MAX);
        x2 = fminf(fmaxf(x2, 0.0f), IMG_MAX);
        y2 = fminf(fmaxf(y2, 0.0f), IMG_MAX);

        flag = (__fsub_rn(x2, x1) >= MIN_SIZE) &&
               (__fsub_rn(y2, y1) >= MIN_SIZE) &&
               (score >= 0.0f);
        rbox = make_float4(x1, y1, x2, y2);
        g_rawbox[il * 1024 + tid] = rbox;
        g_rawsc [il * 1024 + tid] = score;

        const float off = (float)lvl * 801.0f;
        float ox1 = __fadd_rn(x1, off);
        float oy1 = __fadd_rn(y1, off);
        float ox2 = __fadd_rn(x2, off);
        float oy2 = __fadd_rn(y2, off);
        obox = make_float4(ox1, oy1, ox2, oy2);
        area = __fmul_rn(__fsub_rn(ox2, ox1), __fsub_rn(oy2, oy1));
    }
    int m;
    int pos = block_scan_flag(flag, &m);
    if (flag) {
        const int gb = il * 1024 + pos;
        g_nbox [gb] = obox;
        g_narea[gb] = area;
        // key = score desc, tie-break by global position asc (same as R2..R5)
        const int gpos = c_soff[lvl] + tid;
        g_nkey [gb] = ((unsigned long long)mono_key(score) << 13) | (unsigned)(8191 - gpos);
        g_npos [gb] = tid;
    }
    if (tid == 0) g_ncnt[il] = m;
}

// ============ K2: suppression bit-matrix build (massively parallel) ==========
// grid (32, N_IMG*N_LVL), block 256. Block b handles rows i ≡ (b*8+w) mod 256.
__global__ void build_kernel() {
    __shared__ float4 sbox[1024];
    __shared__ float  sarea[1024];
    const int il = blockIdx.y;
    const int b  = blockIdx.x;
    const int tid = threadIdx.x;
    const int lane = tid & 31;
    const int wrp  = tid >> 5;

    const int m = g_ncnt[il];
    for (int i = tid; i < m; i += 256) {
        sbox[i]  = g_nbox [il * 1024 + i];
        sarea[i] = g_narea[il * 1024 + i];
    }
    __syncthreads();

    const int nchunks = (m + 31) >> 5;
    unsigned* mbase = &g_mask[il * 32768];

    for (int i = b * 8 + wrp; i < m; i += 256) {
        const float4 bi = sbox[i];
        const float ai = sarea[i];
        for (int w = i >> 5; w < nchunks; ++w) {
            const int j = (w << 5) + lane;
            bool sup = false;
            if (j > i && j < m) {
                float4 bj = sbox[j];
                float lx = fmaxf(bi.x, bj.x), ly = fmaxf(bi.y, bj.y);
                float rx = fminf(bi.z, bj.z), ry = fminf(bi.w, bj.w);
                float wx = fmaxf(__fsub_rn(rx, lx), 0.0f);
                float wy = fmaxf(__fsub_rn(ry, ly), 0.0f);
                float inter = __fmul_rn(wx, wy);
                if (inter > 0.0f) {
                    float denom = __fadd_rn(__fsub_rn(__fadd_rn(ai, sarea[j]), inter), 1e-9f);
                    float iou = __fdiv_rn(inter, denom);
                    sup = iou > NMS_THRESH;
                }
            }
            unsigned bits = __ballot_sync(0xffffffffu, sup);
            if (lane == 0) mbase[w * 1024 + i] = bits;
        }
    }
}

// ============ K3: chunked greedy resolve + kept-list compaction ===============
__global__ void resolve_kernel() {
    extern __shared__ unsigned smask[];     // [32][1024] staged mask (128KB)
    __shared__ unsigned ssup[32];
    __shared__ unsigned skept[32];
    const int il = blockIdx.x;
    const int tid = threadIdx.x;
    const int lane = tid & 31;
    const int wrp  = tid >> 5;

    const int m = g_ncnt[il];
    const int nchunks = (m + 31) >> 5;
    const unsigned* mbase = &g_mask[il * 32768];

    for (int idx = tid; idx < nchunks * 1024; idx += 1024)
        smask[idx] = mbase[idx];
    if (tid < 32) { ssup[tid] = 0u; skept[tid] = 0u; }
    __syncthreads();

    for (int c = 0; c < nchunks; ++c) {
        if (tid == 0) {
            unsigned sup = ssup[c];
            unsigned kept = 0u;
            const int jmax = min(32, m - (c << 5));
            const unsigned* diag = &smask[c * 1024 + (c << 5)];
            for (int j = 0; j < jmax; ++j) {
                if (!((sup >> j) & 1u)) {
                    kept |= 1u << j;
                    sup |= diag[j];
                }
            }
            skept[c] = kept;
        }
        __syncthreads();
        const int wfut = c + 1 + wrp;
        if (wfut < nchunks) {
            unsigned kept = skept[c];
            unsigned v = ((kept >> lane) & 1u) ? smask[wfut * 1024 + (c << 5) + lane] : 0u;
            unsigned red = __reduce_or_sync(0xffffffffu, v);
            if (lane == 0) ssup[wfut] |= red;
        }
        __syncthreads();
    }

    bool kflag = (tid < m) && ((skept[tid >> 5] >> (tid & 31)) & 1u);
    int mkept;
    int kpos = block_scan_flag(kflag, &mkept);
    if (kflag) {
        g_kept_key[il * 1024 + kpos] = g_nkey[il * 1024 + tid];
        g_kept_p  [il * 1024 + kpos] = g_npos[il * 1024 + tid];
    }
    if (tid == 0) g_kept_cnt[il] = mkept;
}

// ============ K4: merge-rank kept lists + write outputs =======================
__global__ void out_kernel(float* __restrict__ out) {
    __shared__ unsigned long long skeys[N_LVL * 1024];   // 40KB
    __shared__ int cnt[N_LVL];
    const int il = blockIdx.x;
    const int img = il / N_LVL;
    const int L   = il % N_LVL;
    const int tid = threadIdx.x;
    float* out_b = out + img * (POST_NMS * 4);
    float* out_s = out + N_IMG * POST_NMS * 4 + img * POST_NMS;

    if (tid < N_LVL) cnt[tid] = g_kept_cnt[img * N_LVL + tid];
    __syncthreads();
    for (int l = 0; l < N_LVL; ++l)
        for (int i = tid; i < cnt[l]; i += 1024)
            skeys[l * 1024 + i] = g_kept_key[(img * N_LVL + l) * 1024 + i];
    __syncthreads();

    const int myc = cnt[L];
    for (int i = tid; i < myc; i += 1024) {
        const unsigned long long key = skeys[L * 1024 + i];
        int rank = i;
        #pragma unroll
        for (int L2 = 0; L2 < N_LVL; ++L2) {
            if (L2 == L) continue;
            const unsigned long long* a = &skeys[L2 * 1024];
            int lo = 0, hi = cnt[L2];
            while (lo < hi) {
                int mid = (lo + hi) >> 1;
                if (a[mid] > key) lo = mid + 1; else hi = mid;
            }
            rank += lo;
        }
        if (rank < POST_NMS) {
            const int p = g_kept_p[il * 1024 + i];
            float4 bx = g_rawbox[il * 1024 + p];
            out_b[rank * 4 + 0] = bx.x;
            out_b[rank * 4 + 1] = bx.y;
            out_b[rank * 4 + 2] = bx.z;
            out_b[rank * 4 + 3] = bx.w;
            out_s[rank] = g_rawsc[il * 1024 + p];
        }
    }
}

// ---------------- launch -----------------------------------------------------
extern "C" void kernel_launch(void* const* d_in, const int* in_sizes, int n_in,
                              void* d_out, int out_size) {
    const float* objectness = (const float*)d_in[0];   // [2, 159882]
    const float* deltas     = (const float*)d_in[1];   // [2, 159882, 4]
    const float* anchors    = (const float*)d_in[2];   // [159882, 4]
    float* out = (float*)d_out;                        // boxes [2,1000,4] ++ scores [2,1000]

    const int mask_bytes = 32 * 1024 * (int)sizeof(unsigned);   // 128KB
    cudaFuncSetAttribute(resolve_kernel, cudaFuncAttributeMaxDynamicSharedMemorySize, mask_bytes);

    topk_decode_kernel<<<N_IMG * N_LVL, 1024>>>(objectness, deltas, anchors, out);
    build_kernel<<<dim3(32, N_IMG * N_LVL), 256>>>();
    resolve_kernel<<<N_IMG * N_LVL, 1024, mask_bytes>>>();
    out_kernel<<<N_IMG * N_LVL, 1024>>>(out);
}